// round 6
// baseline (speedup 1.0000x reference)
#include <cuda_runtime.h>
#include <cuda_bf16.h>
#include <math.h>

typedef unsigned long long u64;

// Problem constants (fixed by the dataset)
#define BB 2
#define HH 12
#define SS 3456
#define DD 32
#define FPT 216           // feats per timestep
#define NT (SS / FPT)     // 16 timesteps
#define WIN 8
#define IMG_START 20      // FPT - img_feat_size(196)
#define JOINT_START 4     // IMG_START - act_size(16)
#define NPAST 19          // valid past kv_m: {0,1,2,3,5..19}
#define MAXPAST ((WIN - 1) * NPAST)   // 133

// scale * log2(e): ex2.approx(dot) == exp(dot/sqrt(32))
#define SCL2E (0.17677669529663689f * 1.4426950408889634f)

#define THREADS 256       // 216 mains + 40 B-helpers

// smem layout (floats / bytes). Same-t IMG K/V rows are NOT staged (helpers
// stream them from global) -> tile shrinks 103KB -> ~44.6KB -> 3 blocks/SM.
#define OFF_SK20 0
#define OFF_SV20 (IMG_START * DD)                    // 640
#define OFF_PK   (2 * IMG_START * DD)                // 1280
#define OFF_PV   (2 * IMG_START * DD + MAXPAST * DD) // 5536
#define TILE_FLOATS (2 * IMG_START * DD + 2 * MAXPAST * DD)  // 9792
#define TILE_BYTES (TILE_FLOATS * 4)                 // 39168 (8B aligned)
#define NPARTS 40
#define PART_U64 17                                  // 16 acc(u64) + lsum
#define SMEM_BYTES (TILE_BYTES + NPARTS * PART_U64 * 8)  // 44608

__device__ __forceinline__ u64 fma2(u64 a, u64 b, u64 c) {
    u64 d; asm("fma.rn.f32x2 %0, %1, %2, %3;" : "=l"(d) : "l"(a), "l"(b), "l"(c)); return d;
}
__device__ __forceinline__ u64 pack2(float lo, float hi) {
    u64 d; asm("mov.b64 %0, {%1, %2};" : "=l"(d) : "f"(lo), "f"(hi)); return d;
}
__device__ __forceinline__ void unpack2(u64 a, float& lo, float& hi) {
    asm("mov.b64 {%0, %1}, %2;" : "=f"(lo), "=f"(hi) : "l"(a));
}
__device__ __forceinline__ float ex2(float x) {
    float r; asm("ex2.approx.f32 %0, %1;" : "=f"(r) : "f"(x)); return r;
}

__global__ void __launch_bounds__(THREADS, 3)
eye_attn_kernel(const float* __restrict__ q,
                const float* __restrict__ k,
                const float* __restrict__ v,
                float* __restrict__ out)
{
    extern __shared__ float smem[];
    float* sK20 = smem + OFF_SK20;
    float* sV20 = smem + OFF_SV20;
    float* pK   = smem + OFF_PK;
    float* pV   = smem + OFF_PV;
    u64*   part = (u64*)((char*)smem + TILE_BYTES);

    const int t = blockIdx.x;
    const int h = blockIdx.y;
    const int b = blockIdx.z;
    const int tid = threadIdx.x;

    const size_t bh_base = ((size_t)(b * HH + h)) * SS * DD;
    const float* kg = k + bh_base + (size_t)t * FPT * DD;   // same-t K rows
    const float* vg = v + bh_base + (size_t)t * FPT * DD;   // same-t V rows

    // ---- stage same-t K/V rows 0..19 (the only same-t rows every query needs) ----
    {
        const float4* kg4 = (const float4*)kg;
        const float4* vg4 = (const float4*)vg;
        float4* sK4 = (float4*)sK20;
        float4* sV4 = (float4*)sV20;
        for (int i = tid; i < IMG_START * DD / 4; i += THREADS) {  // 160 float4
            sK4[i] = kg4[i];
            sV4[i] = vg4[i];
        }
    }

    const int npt = (t < WIN - 1) ? t : (WIN - 1);   // # past timesteps
    const int npk = npt * NPAST;                     // # valid past rows
    const int n4  = npt * 4;                         // # joint-visible past rows

    // ---- stage compacted past K/V rows, JOINT-FIRST order ----
    // rows [0, n4)   : m in {0,1,2,3}  (visible to all queries)
    // rows [n4, npk) : m in {5..19}    (invisible to joint queries)
    {
        const int ntask = npk * 8;                   // 8 float4 per row
        for (int r4 = tid; r4 < ntask; r4 += THREADS) {
            const int r = r4 >> 3;
            const int c = r4 & 7;
            int dt, m;
            if (r < n4) { dt = (r >> 2) + 1;          m = r & 3; }
            else        { const int r2 = r - n4;
                          dt = r2 / 15 + 1;           m = 5 + r2 - (dt - 1) * 15; }
            const size_t src = bh_base + ((size_t)(t - dt) * FPT + m) * DD;
            ((float4*)pK)[r * 8 + c] = ((const float4*)(k + src))[c];
            ((float4*)pV)[r * 8 + c] = ((const float4*)(v + src))[c];
        }
    }

    __syncthreads();

    // ---- roles ----
    // tid   0..215 : main for query tid. Phase A (same-t keys 0..19, smem) +
    //                bulk (past rows, smem; joint queries bound n4).
    // tid 216..255 : B-helper idx=tid-216 for query idx>>1, half=idx&1:
    //                bulk = 98 same-t IMG keys [20+half*98 ...), streamed from GLOBAL.
    const bool main_ = (tid < FPT);
    const int  bidx  = tid - FPT;
    const int  qrow  = main_ ? tid : (bidx >> 1);
    const bool qjoint = (qrow >= JOINT_START) && (qrow < IMG_START);

    // unified per-lane bulk task (generic pointers: smem for mains, global for helpers)
    const float* kb; const float* vb; int bn;
    if (main_) {
        kb = pK; vb = pV;
        bn = qjoint ? n4 : npk;
    } else {
        const int row0 = IMG_START + (bidx & 1) * 98;
        kb = kg + (size_t)row0 * DD;
        vb = vg + (size_t)row0 * DD;
        bn = 98;
    }

    // ---- load q row, pre-scaled by scale*log2e, packed f32x2 ----
    u64 q2[16];
    {
        const float4* qg4 = (const float4*)(q + bh_base + ((size_t)t * FPT + qrow) * DD);
        #pragma unroll
        for (int i = 0; i < 8; i++) {
            float4 x = qg4[i];
            q2[2 * i]     = pack2(x.x * SCL2E, x.y * SCL2E);
            q2[2 * i + 1] = pack2(x.z * SCL2E, x.w * SCL2E);
        }
    }

    u64 acc[16];
    #pragma unroll
    for (int i = 0; i < 16; i++) acc[i] = 0ull;
    float lsum = 0.0f;
    const u64 one2 = pack2(1.0f, 1.0f);

    auto doKey = [&](const float* krow, const float* vrow) {
        const ulonglong2* k2 = (const ulonglong2*)krow;
        u64 sA = 0ull, sB = 0ull, sC = 0ull, sD = 0ull;
        ulonglong2 kk;
        kk = k2[0]; sA = fma2(q2[0],  kk.x, sA); sB = fma2(q2[1],  kk.y, sB);
        kk = k2[1]; sC = fma2(q2[2],  kk.x, sC); sD = fma2(q2[3],  kk.y, sD);
        kk = k2[2]; sA = fma2(q2[4],  kk.x, sA); sB = fma2(q2[5],  kk.y, sB);
        kk = k2[3]; sC = fma2(q2[6],  kk.x, sC); sD = fma2(q2[7],  kk.y, sD);
        kk = k2[4]; sA = fma2(q2[8],  kk.x, sA); sB = fma2(q2[9],  kk.y, sB);
        kk = k2[5]; sC = fma2(q2[10], kk.x, sC); sD = fma2(q2[11], kk.y, sD);
        kk = k2[6]; sA = fma2(q2[12], kk.x, sA); sB = fma2(q2[13], kk.y, sB);
        kk = k2[7]; sC = fma2(q2[14], kk.x, sC); sD = fma2(q2[15], kk.y, sD);
        u64 sAB = fma2(sA, one2, sB);
        u64 sCD = fma2(sC, one2, sD);
        u64 sT  = fma2(sAB, one2, sCD);
        float lo, hi; unpack2(sT, lo, hi);
        const float p = ex2(lo + hi);
        lsum += p;
        const u64 p2 = pack2(p, p);
        const ulonglong2* v2 = (const ulonglong2*)vrow;
        ulonglong2 vv;
        vv = v2[0]; acc[0]  = fma2(p2, vv.x, acc[0]);  acc[1]  = fma2(p2, vv.y, acc[1]);
        vv = v2[1]; acc[2]  = fma2(p2, vv.x, acc[2]);  acc[3]  = fma2(p2, vv.y, acc[3]);
        vv = v2[2]; acc[4]  = fma2(p2, vv.x, acc[4]);  acc[5]  = fma2(p2, vv.y, acc[5]);
        vv = v2[3]; acc[6]  = fma2(p2, vv.x, acc[6]);  acc[7]  = fma2(p2, vv.y, acc[7]);
        vv = v2[4]; acc[8]  = fma2(p2, vv.x, acc[8]);  acc[9]  = fma2(p2, vv.y, acc[9]);
        vv = v2[5]; acc[10] = fma2(p2, vv.x, acc[10]); acc[11] = fma2(p2, vv.y, acc[11]);
        vv = v2[6]; acc[12] = fma2(p2, vv.x, acc[12]); acc[13] = fma2(p2, vv.y, acc[13]);
        vv = v2[7]; acc[14] = fma2(p2, vv.x, acc[14]); acc[15] = fma2(p2, vv.y, acc[15]);
    };

    // Phase A: same-t keys 0..19, pure smem (mains only; helper lanes predicated
    // off with an empty else -> no serialization in the mixed warp)
    if (main_) {
        #pragma unroll 2
        for (int j = 0; j < IMG_START; j++)
            doKey(sK20 + j * DD, sV20 + j * DD);
    }

    // Unified bulk loop: per-lane base/bound; mixed warps run to max bound,
    // finished lanes predicated off. Generic loads route per-lane (smem/global).
    #pragma unroll 2
    for (int r = 0; r < bn; r++)
        doKey(kb + (size_t)r * DD, vb + (size_t)r * DD);

    // helpers publish partials
    if (!main_) {
        u64* pp = part + bidx * PART_U64;
        #pragma unroll
        for (int i = 0; i < 16; i++) pp[i] = acc[i];
        ((float*)pp)[32] = lsum;
    }

    __syncthreads();

    if (main_) {
        if (tid < IMG_START) {
            // queries 0..19: add the two B-helper partials (same-t IMG keys)
            #pragma unroll
            for (int hB = 0; hB < 2; hB++) {
                u64* pp = part + (2 * tid + hB) * PART_U64;
                #pragma unroll
                for (int i = 0; i < 16; i++) acc[i] = fma2(pp[i], one2, acc[i]);
                lsum += ((float*)pp)[32];
            }
        }
        // ---- write out ----
        const float inv = 1.0f / lsum;
        float4* og4 = (float4*)(out + bh_base + ((size_t)t * FPT + tid) * DD);
        #pragma unroll
        for (int i = 0; i < 8; i++) {
            float a0, a1, a2, a3;
            unpack2(acc[2 * i], a0, a1);
            unpack2(acc[2 * i + 1], a2, a3);
            float4 o;
            o.x = a0 * inv; o.y = a1 * inv; o.z = a2 * inv; o.w = a3 * inv;
            og4[i] = o;
        }
    }
}

extern "C" void kernel_launch(void* const* d_in, const int* in_sizes, int n_in,
                              void* d_out, int out_size)
{
    const float* q = (const float*)d_in[0];
    const float* k = (const float*)d_in[1];
    const float* v = (const float*)d_in[2];
    float* out = (float*)d_out;

    cudaFuncSetAttribute(eye_attn_kernel,
                         cudaFuncAttributeMaxDynamicSharedMemorySize, SMEM_BYTES);

    dim3 grid(NT, HH, BB);   // (16, 12, 2)
    eye_attn_kernel<<<grid, THREADS, SMEM_BYTES>>>(q, k, v, out);
}